// round 9
// baseline (speedup 1.0000x reference)
#include <cuda_runtime.h>
#include <cuda_bf16.h>
#include <math_constants.h>
#include <cstdint>

// Problem constants
#define PB 2
#define PS 2048
#define PE 1024
#define PH 16
#define PHD 64
#define PBH (PB * PH)        // 32
#define PM (PB * PS)         // 4096

// ---------------------------------------------------------------------------
// PTX helpers (sm_100-safe: mma.sync only, NO tcgen05 — ptxas targets compute_100)
// ---------------------------------------------------------------------------
__device__ __forceinline__ uint32_t f2tf32(float f) {
    uint32_t u; asm("cvt.rna.tf32.f32 %0, %1;" : "=r"(u) : "f"(f)); return u;
}
__device__ __forceinline__ void mma_tf32(float c[4], const uint32_t a[4], const uint32_t b[2]) {
    asm("mma.sync.aligned.m16n8k8.row.col.f32.tf32.tf32.f32 "
        "{%0,%1,%2,%3}, {%4,%5,%6,%7}, {%8,%9}, {%0,%1,%2,%3};"
        : "+f"(c[0]), "+f"(c[1]), "+f"(c[2]), "+f"(c[3])
        : "r"(a[0]), "r"(a[1]), "r"(a[2]), "r"(a[3]), "r"(b[0]), "r"(b[1]));
}

// ---------------------------------------------------------------------------
// Scratch (no cudaMalloc allowed)
// ---------------------------------------------------------------------------
__device__ float g_qp[PM * PE];
__device__ float g_kp[PM * PE];
__device__ float g_vp[PM * PE];
__device__ float g_ao[PM * PE];

// ---------------------------------------------------------------------------
// TF32 GEMM v3: C[M,N] = A[M,K] @ B[N,K]^T  (torch Linear)
// CTA 128x128, 4 warps (2x2), warp tile 64x64 -> 16 FLOP/smem-byte.
// 128 threads => 2 CTAs/SM (independent pipelines for latency hiding).
// K-tile 16, double-buffered, LDG register prefetch, tf32 cvt at staging.
// Pitch 20: fragment bank = (20*gr + cc) mod 32 -> 8 quads cover all banks.
// ---------------------------------------------------------------------------
#define GP 20
#define SMT (128 * GP)                  // floats per (A or B) buffer
#define GT_SMEM (SMT * 4 * 4 * 2 / 2)   // 2 buffers * (A+B) * 4B = 81920... computed below
#define GT_SMEM_BYTES (2 * (SMT + SMT) * 4)   // 40960 bytes

__global__ __launch_bounds__(128, 2)
void gemm_tc(const float* __restrict__ A0, const float* __restrict__ B0, float* __restrict__ C0,
             const float* __restrict__ A1, const float* __restrict__ B1, float* __restrict__ C1,
             const float* __restrict__ A2, const float* __restrict__ B2, float* __restrict__ C2,
             int M, int N, int K)
{
    __shared__ float Sm[2][2 * SMT];    // [buf][A(128*20) | B(128*20)]

    const float* A = A0; const float* B = B0; float* C = C0;
    if (blockIdx.z == 1) { A = A1; B = B1; C = C1; }
    else if (blockIdx.z == 2) { A = A2; B = B2; C = C2; }

    const int tid  = threadIdx.x;
    const int lane = tid & 31;
    const int warp = tid >> 5;          // 0..3
    const int wm   = warp >> 1;         // 0..1
    const int wn   = warp & 1;          // 0..1
    const int gr   = lane >> 2;         // 0..7
    const int cc   = lane & 3;          // 0..3

    const int bm = blockIdx.y * 128;
    const int bn = blockIdx.x * 128;

    // loader: thread t stages A row t and B row t, 16 k-floats each
    const float* Agp = A + (size_t)(bm + tid) * K;
    const float* Bgp = B + (size_t)(bn + tid) * K;
    float* AsD = &Sm[0][tid * GP];
    float* BsD = &Sm[0][SMT + tid * GP];

    float acc[4][8][4];
#pragma unroll
    for (int mt = 0; mt < 4; mt++)
#pragma unroll
        for (int nt = 0; nt < 8; nt++)
#pragma unroll
            for (int r = 0; r < 4; r++) acc[mt][nt][r] = 0.f;

    // prefetch tile 0
    float4 pa[2], pb[2];
#pragma unroll
    for (int i = 0; i < 2; i++) {
        pa[i] = *(const float4*)(Agp + i * 8 + ((i & 1) ? 4 : 0));   // see note below
        pb[i] = *(const float4*)(Bgp + i * 8 + ((i & 1) ? 4 : 0));
    }
    // NOTE: layout trick above is wrong-prone; use straightforward 4x float4:
    float4 qa0 = *(const float4*)(Agp + 0),  qa1 = *(const float4*)(Agp + 4);
    float4 qa2 = *(const float4*)(Agp + 8),  qa3 = *(const float4*)(Agp + 12);
    float4 qb0 = *(const float4*)(Bgp + 0),  qb1 = *(const float4*)(Bgp + 4);
    float4 qb2 = *(const float4*)(Bgp + 8),  qb3 = *(const float4*)(Bgp + 12);

    auto stage = [&](int buf, float4 a0, float4 a1, float4 a2, float4 a3,
                     float4 b0, float4 b1, float4 b2, float4 b3) {
        float* Ad = &Sm[buf][tid * GP];
        float* Bd = &Sm[buf][SMT + tid * GP];
        Ad[0]  = __uint_as_float(f2tf32(a0.x)); Ad[1]  = __uint_as_float(f2tf32(a0.y));
        Ad[2]  = __uint_as_float(f2tf32(a0.z)); Ad[3]  = __uint_as_float(f2tf32(a0.w));
        Ad[4]  = __uint_as_float(f2tf32(a1.x)); Ad[5]  = __uint_as_float(f2tf32(a1.y));
        Ad[6]  = __uint_as_float(f2tf32(a1.z)); Ad[7]  = __uint_as_float(f2tf32(a1.w));
        Ad[8]  = __uint_as_float(f2tf32(a2.x)); Ad[9]  = __uint_as_float(f2tf32(a2.y));
        Ad[10] = __uint_as_float(f2tf32(a2.z)); Ad[11] = __uint_as_float(f2tf32(a2.w));
        Ad[12] = __uint_as_float(f2tf32(a3.x)); Ad[13] = __uint_as_float(f2tf32(a3.y));
        Ad[14] = __uint_as_float(f2tf32(a3.z)); Ad[15] = __uint_as_float(f2tf32(a3.w));
        Bd[0]  = __uint_as_float(f2tf32(b0.x)); Bd[1]  = __uint_as_float(f2tf32(b0.y));
        Bd[2]  = __uint_as_float(f2tf32(b0.z)); Bd[3]  = __uint_as_float(f2tf32(b0.w));
        Bd[4]  = __uint_as_float(f2tf32(b1.x)); Bd[5]  = __uint_as_float(f2tf32(b1.y));
        Bd[6]  = __uint_as_float(f2tf32(b1.z)); Bd[7]  = __uint_as_float(f2tf32(b1.w));
        Bd[8]  = __uint_as_float(f2tf32(b2.x)); Bd[9]  = __uint_as_float(f2tf32(b2.y));
        Bd[10] = __uint_as_float(f2tf32(b2.z)); Bd[11] = __uint_as_float(f2tf32(b2.w));
        Bd[12] = __uint_as_float(f2tf32(b3.x)); Bd[13] = __uint_as_float(f2tf32(b3.y));
        Bd[14] = __uint_as_float(f2tf32(b3.z)); Bd[15] = __uint_as_float(f2tf32(b3.w));
    };

    stage(0, qa0, qa1, qa2, qa3, qb0, qb1, qb2, qb3);
    __syncthreads();

    const int NT = K / 16;   // 64
    int buf = 0;
    for (int t = 0; t < NT; t++) {
        const bool more = (t + 1 < NT);
        if (more) {
            const float* Ap = Agp + (t + 1) * 16;
            const float* Bp = Bgp + (t + 1) * 16;
            qa0 = *(const float4*)(Ap + 0);  qa1 = *(const float4*)(Ap + 4);
            qa2 = *(const float4*)(Ap + 8);  qa3 = *(const float4*)(Ap + 12);
            qb0 = *(const float4*)(Bp + 0);  qb1 = *(const float4*)(Bp + 4);
            qb2 = *(const float4*)(Bp + 8);  qb3 = *(const float4*)(Bp + 12);
        }

        const float* As = &Sm[buf][0];
        const float* Bs = &Sm[buf][SMT];
#pragma unroll
        for (int ks = 0; ks < 2; ks++) {
            const int k8 = ks * 8;
            uint32_t afr[4][4], bfr[8][2];
#pragma unroll
            for (int mt = 0; mt < 4; mt++) {
                const int r0 = wm * 64 + mt * 16 + gr;
                afr[mt][0] = __float_as_uint(As[r0 * GP + k8 + cc]);
                afr[mt][1] = __float_as_uint(As[(r0 + 8) * GP + k8 + cc]);
                afr[mt][2] = __float_as_uint(As[r0 * GP + k8 + cc + 4]);
                afr[mt][3] = __float_as_uint(As[(r0 + 8) * GP + k8 + cc + 4]);
            }
#pragma unroll
            for (int nt = 0; nt < 8; nt++) {
                const int nr = wn * 64 + nt * 8 + gr;
                bfr[nt][0] = __float_as_uint(Bs[nr * GP + k8 + cc]);
                bfr[nt][1] = __float_as_uint(Bs[nr * GP + k8 + cc + 4]);
            }
#pragma unroll
            for (int mt = 0; mt < 4; mt++)
#pragma unroll
                for (int nt = 0; nt < 8; nt++)
                    mma_tf32(acc[mt][nt], afr[mt], bfr[nt]);
        }

        if (more) {
            const int nb = buf ^ 1;
            stage(nb, qa0, qa1, qa2, qa3, qb0, qb1, qb2, qb3);
            __syncthreads();
            buf = nb;
        }
    }

    // epilogue
#pragma unroll
    for (int mt = 0; mt < 4; mt++) {
        const int r0 = bm + wm * 64 + mt * 16 + gr;
#pragma unroll
        for (int nt = 0; nt < 8; nt++) {
            const int cb = bn + wn * 64 + nt * 8 + 2 * cc;
            *(float2*)(C + (size_t)r0 * N + cb)       = make_float2(acc[mt][nt][0], acc[mt][nt][1]);
            *(float2*)(C + (size_t)(r0 + 8) * N + cb) = make_float2(acc[mt][nt][2], acc[mt][nt][3]);
        }
    }
}

// ---------------------------------------------------------------------------
// Flash attention, tf32 mma.sync (unchanged from R6: working, ~225us)
// ---------------------------------------------------------------------------
#define KSP 68
#define VSP 72
#define PSP 68
#define SM_KS (64 * KSP)
#define SM_VS (64 * VSP)
#define SM_PS (128 * PSP)
#define FLASH_SMEM ((SM_KS + SM_VS + SM_PS) * 4)

__global__ __launch_bounds__(256, 2)
void flash_tc(const float* __restrict__ Q, const float* __restrict__ K,
              const float* __restrict__ V, float* __restrict__ O,
              const int* __restrict__ maskflag)
{
    extern __shared__ float smf[];
    float* Ks = smf;                 // [n][d] pitch 68
    float* Vs = Ks + SM_KS;          // [n][d] pitch 72
    float* Ps = Vs + SM_VS;          // [m][n] pitch 68 (Q staging first)

    const int tid  = threadIdx.x;
    const int lane = tid & 31;
    const int warp = tid >> 5;
    const int gr   = lane >> 2;
    const int cc   = lane & 3;
    const int bh   = blockIdx.y;
    const int bx   = blockIdx.x;
    const int m0   = bx * 128;
    const int wr0  = warp * 16;

    const float* Qb = Q + (size_t)bh * PS * PHD;
    const float* Kb = K + (size_t)bh * PS * PHD;
    const float* Vb = V + (size_t)bh * PS * PHD;
    float*       Ob = O + (size_t)bh * PS * PHD + (size_t)m0 * PHD;

    for (int t = tid; t < 2048; t += 256) {
        int r = t >> 4, c4 = (t & 15) << 2;
        float4 x = *(const float4*)(Qb + (size_t)(m0 + r) * PHD + c4);
        float* d = &Ps[r * PSP + c4];
        d[0] = x.x * 0.125f; d[1] = x.y * 0.125f;
        d[2] = x.z * 0.125f; d[3] = x.w * 0.125f;
    }
    __syncthreads();

    uint32_t qa[8][4];
#pragma unroll
    for (int s = 0; s < 8; s++) {
        const int k8 = s * 8;
        qa[s][0] = f2tf32(Ps[(wr0 + gr) * PSP + k8 + cc]);
        qa[s][1] = f2tf32(Ps[(wr0 + gr + 8) * PSP + k8 + cc]);
        qa[s][2] = f2tf32(Ps[(wr0 + gr) * PSP + k8 + cc + 4]);
        qa[s][3] = f2tf32(Ps[(wr0 + gr + 8) * PSP + k8 + cc + 4]);
    }
    __syncwarp();

    const bool causal = (*maskflag != 0);
    const int ntiles = causal ? (2 * bx + 2) : (PS / 64);

    float mr0 = -1e30f, mr1 = -1e30f, lr0 = 0.f, lr1 = 0.f;
    float o[8][4];
#pragma unroll
    for (int nt = 0; nt < 8; nt++)
#pragma unroll
        for (int r = 0; r < 4; r++) o[nt][r] = 0.f;

    for (int kt = 0; kt < ntiles; kt++) {
        const int n0 = kt * 64;

        for (int t = tid; t < 1024; t += 256) {
            int r = t >> 4, c4 = (t & 15) << 2;
            float4 xk = *(const float4*)(Kb + (size_t)(n0 + r) * PHD + c4);
            float* kd = &Ks[r * KSP + c4];
            kd[0] = __uint_as_float(f2tf32(xk.x)); kd[1] = __uint_as_float(f2tf32(xk.y));
            kd[2] = __uint_as_float(f2tf32(xk.z)); kd[3] = __uint_as_float(f2tf32(xk.w));
            float4 xv = *(const float4*)(Vb + (size_t)(n0 + r) * PHD + c4);
            float* vd = &Vs[r * VSP + c4];
            vd[0] = __uint_as_float(f2tf32(xv.x)); vd[1] = __uint_as_float(f2tf32(xv.y));
            vd[2] = __uint_as_float(f2tf32(xv.z)); vd[3] = __uint_as_float(f2tf32(xv.w));
        }
        __syncthreads();

        float s[8][4];
#pragma unroll
        for (int nt = 0; nt < 8; nt++)
#pragma unroll
            for (int r = 0; r < 4; r++) s[nt][r] = 0.f;

#pragma unroll
        for (int ks = 0; ks < 8; ks++) {
            const int k8 = ks * 8;
#pragma unroll
            for (int nt = 0; nt < 8; nt++) {
                uint32_t b[2];
                b[0] = __float_as_uint(Ks[(nt * 8 + gr) * KSP + k8 + cc]);
                b[1] = __float_as_uint(Ks[(nt * 8 + gr) * KSP + k8 + cc + 4]);
                mma_tf32(s[nt], qa[ks], b);
            }
        }

        const int rlo = m0 + wr0 + gr;
        const int rhi = rlo + 8;
        if (causal && (n0 + 63 > rlo)) {
#pragma unroll
            for (int nt = 0; nt < 8; nt++) {
                const int c0 = n0 + nt * 8 + 2 * cc;
                if (c0 > rlo)     s[nt][0] = -1e30f;
                if (c0 + 1 > rlo) s[nt][1] = -1e30f;
                if (c0 > rhi)     s[nt][2] = -1e30f;
                if (c0 + 1 > rhi) s[nt][3] = -1e30f;
            }
        }

        float tl = -1e30f, th = -1e30f;
#pragma unroll
        for (int nt = 0; nt < 8; nt++) {
            tl = fmaxf(tl, fmaxf(s[nt][0], s[nt][1]));
            th = fmaxf(th, fmaxf(s[nt][2], s[nt][3]));
        }
        tl = fmaxf(tl, __shfl_xor_sync(0xffffffffu, tl, 1));
        tl = fmaxf(tl, __shfl_xor_sync(0xffffffffu, tl, 2));
        th = fmaxf(th, __shfl_xor_sync(0xffffffffu, th, 1));
        th = fmaxf(th, __shfl_xor_sync(0xffffffffu, th, 2));

        const float mn0 = fmaxf(mr0, tl);
        const float mn1 = fmaxf(mr1, th);
        const float al0 = __expf(mr0 - mn0);
        const float al1 = __expf(mr1 - mn1);

        float sl = 0.f, sh = 0.f;
#pragma unroll
        for (int nt = 0; nt < 8; nt++) {
            float p0 = __expf(s[nt][0] - mn0);
            float p1 = __expf(s[nt][1] - mn0);
            float p2 = __expf(s[nt][2] - mn1);
            float p3 = __expf(s[nt][3] - mn1);
            sl += p0 + p1; sh += p2 + p3;
            uint2 w0 = make_uint2(f2tf32(p0), f2tf32(p1));
            uint2 w1 = make_uint2(f2tf32(p2), f2tf32(p3));
            *(uint2*)&Ps[(wr0 + gr) * PSP + nt * 8 + 2 * cc]     = w0;
            *(uint2*)&Ps[(wr0 + gr + 8) * PSP + nt * 8 + 2 * cc] = w1;
        }
        sl += __shfl_xor_sync(0xffffffffu, sl, 1);
        sl += __shfl_xor_sync(0xffffffffu, sl, 2);
        sh += __shfl_xor_sync(0xffffffffu, sh, 1);
        sh += __shfl_xor_sync(0xffffffffu, sh, 2);

        lr0 = lr0 * al0 + sl;
        lr1 = lr1 * al1 + sh;
        mr0 = mn0; mr1 = mn1;

#pragma unroll
        for (int nt = 0; nt < 8; nt++) {
            o[nt][0] *= al0; o[nt][1] *= al0;
            o[nt][2] *= al1; o[nt][3] *= al1;
        }
        __syncwarp();

#pragma unroll
        for (int ks = 0; ks < 8; ks++) {
            const int k8 = ks * 8;
            uint32_t a[4];
            a[0] = __float_as_uint(Ps[(wr0 + gr) * PSP + k8 + cc]);
            a[1] = __float_as_uint(Ps[(wr0 + gr + 8) * PSP + k8 + cc]);
            a[2] = __float_as_uint(Ps[(wr0 + gr) * PSP + k8 + cc + 4]);
            a[3] = __float_as_uint(Ps[(wr0 + gr + 8) * PSP + k8 + cc + 4]);
#pragma unroll
            for (int nt = 0; nt < 8; nt++) {
                uint32_t b[2];
                b[0] = __float_as_uint(Vs[(k8 + cc) * VSP + nt * 8 + gr]);
                b[1] = __float_as_uint(Vs[(k8 + cc + 4) * VSP + nt * 8 + gr]);
                mma_tf32(o[nt], a, b);
            }
        }
        __syncthreads();
    }

    const float i0 = 1.0f / lr0;
    const float i1 = 1.0f / lr1;
#pragma unroll
    for (int nt = 0; nt < 8; nt++) {
        const int cb = nt * 8 + 2 * cc;
        *(float2*)(Ob + (size_t)(wr0 + gr) * PHD + cb) =
            make_float2(o[nt][0] * i0, o[nt][1] * i0);
        *(float2*)(Ob + (size_t)(wr0 + gr + 8) * PHD + cb) =
            make_float2(o[nt][2] * i1, o[nt][3] * i1);
    }
}

// ---------------------------------------------------------------------------
// Launch
// ---------------------------------------------------------------------------
extern "C" void kernel_launch(void* const* d_in, const int* in_sizes, int n_in,
                              void* d_out, int out_size)
{
    const float* q  = (const float*)d_in[0];
    const float* k  = (const float*)d_in[1];
    const float* v  = (const float*)d_in[2];
    const float* wq = (const float*)d_in[3];
    const float* wk = (const float*)d_in[4];
    const float* wv = (const float*)d_in[5];
    const float* wo = (const float*)d_in[6];
    const int*   am = (const int*)d_in[7];
    float* out = (float*)d_out;

    float *qp, *kp, *vp, *ao;
    cudaGetSymbolAddress((void**)&qp, g_qp);
    cudaGetSymbolAddress((void**)&kp, g_kp);
    cudaGetSymbolAddress((void**)&vp, g_vp);
    cudaGetSymbolAddress((void**)&ao, g_ao);

    cudaFuncSetAttribute(flash_tc, cudaFuncAttributeMaxDynamicSharedMemorySize, FLASH_SMEM);

    // fused Q/K/V projections (z = 0,1,2)
    dim3 gQKV(PE / 128, PM / 128, 3);   // (8, 32, 3)
    gemm_tc<<<gQKV, 128>>>(q, wq, qp,  k, wk, kp,  v, wv, vp, PM, PE, PE);

    dim3 gAttn(PS / 128, PBH);          // (16, 32)
    flash_tc<<<gAttn, 256, FLASH_SMEM>>>(qp, kp, vp, ao, am);

    // output projection
    dim3 gO(PE / 128, PM / 128, 1);
    gemm_tc<<<gO, 128>>>(ao, wo, out,  ao, wo, out,  ao, wo, out, PM, PE, PE);
}

// round 10
// speedup vs baseline: 1.0171x; 1.0171x over previous
#include <cuda_runtime.h>
#include <cuda_bf16.h>
#include <math_constants.h>
#include <cstdint>

// Problem constants
#define PB 2
#define PS 2048
#define PE 1024
#define PH 16
#define PHD 64
#define PBH (PB * PH)        // 32
#define PM (PB * PS)         // 4096

// ---------------------------------------------------------------------------
// helpers (sm_100-safe: mma.sync only)
// ---------------------------------------------------------------------------
__device__ __forceinline__ uint32_t f2tf32(float f) {
    uint32_t u; asm("cvt.rna.tf32.f32 %0, %1;" : "=r"(u) : "f"(f)); return u;
}
__device__ __forceinline__ void mma_tf32(float c[4], const uint32_t a[4], const uint32_t b[2]) {
    asm("mma.sync.aligned.m16n8k8.row.col.f32.tf32.tf32.f32 "
        "{%0,%1,%2,%3}, {%4,%5,%6,%7}, {%8,%9}, {%0,%1,%2,%3};"
        : "+f"(c[0]), "+f"(c[1]), "+f"(c[2]), "+f"(c[3])
        : "r"(a[0]), "r"(a[1]), "r"(a[2]), "r"(a[3]), "r"(b[0]), "r"(b[1]));
}

// ---------------------------------------------------------------------------
// Scratch (no cudaMalloc allowed)
// ---------------------------------------------------------------------------
__device__ float g_qp[PM * PE];
__device__ float g_kp[PM * PE];
__device__ float g_vp[PM * PE];
__device__ float g_ao[PM * PE];

// ---------------------------------------------------------------------------
// TF32 GEMM (R6 structure + permuted-k smem):
// C[M,N] = A[M,K] @ B[N,K]^T. CTA 128x128, 8 warps (2x4), warp tile 64x32,
// K-tile 32, pitch 36. Within each k8 block smem holds k-order
// {0,4,1,5,2,6,3,7} so a lane's (cc, cc+4) pair is one LDS.64 and staging
// is 4x STS.128 per matrix. Permutation applied to A and B: k-sum invariant.
// ---------------------------------------------------------------------------
#define GP 36   // smem pitch (floats)

__global__ __launch_bounds__(256, 2)
void gemm_tf32(const float* __restrict__ A0, const float* __restrict__ B0, float* __restrict__ C0,
               const float* __restrict__ A1, const float* __restrict__ B1, float* __restrict__ C1,
               const float* __restrict__ A2, const float* __restrict__ B2, float* __restrict__ C2,
               int M, int N, int K)
{
    __shared__ uint32_t As[128 * GP];
    __shared__ uint32_t Bs[128 * GP];

    const float* A = A0; const float* B = B0; float* C = C0;
    if (blockIdx.z == 1) { A = A1; B = B1; C = C1; }
    else if (blockIdx.z == 2) { A = A2; B = B2; C = C2; }

    const int tid  = threadIdx.x;
    const int lane = tid & 31;
    const int warp = tid >> 5;
    const int wm   = warp >> 2;          // 0..1
    const int wn   = warp & 3;           // 0..3
    const int gr   = lane >> 2;          // 0..7
    const int cc   = lane & 3;           // 0..3

    const int bm = blockIdx.y * 128;
    const int bn = blockIdx.x * 128;

    const int lr = tid >> 1;             // 0..127
    const int lq = (tid & 1) * 16;       // 0 or 16

    const float* Ap = A + (size_t)(bm + lr) * K + lq;
    const float* Bp = B + (size_t)(bn + lr) * K + lq;

    float acc[4][4][4];
#pragma unroll
    for (int mt = 0; mt < 4; mt++)
#pragma unroll
        for (int nt = 0; nt < 4; nt++)
#pragma unroll
            for (int r = 0; r < 4; r++) acc[mt][nt][r] = 0.f;

    float4 pa[4], pb[4];
#pragma unroll
    for (int i = 0; i < 4; i++) {
        pa[i] = *(const float4*)(Ap + i * 4);
        pb[i] = *(const float4*)(Bp + i * 4);
    }

    for (int k0 = 0; k0 < K; k0 += 32) {
        // permuted staging: block {x0..w0 | x1..w1} -> (x0,x1,y0,y1),(z0,z1,w0,w1)
        uint32_t* Ad = &As[lr * GP + lq];
        uint32_t* Bd = &Bs[lr * GP + lq];
        *(uint4*)(Ad + 0)  = make_uint4(f2tf32(pa[0].x), f2tf32(pa[1].x), f2tf32(pa[0].y), f2tf32(pa[1].y));
        *(uint4*)(Ad + 4)  = make_uint4(f2tf32(pa[0].z), f2tf32(pa[1].z), f2tf32(pa[0].w), f2tf32(pa[1].w));
        *(uint4*)(Ad + 8)  = make_uint4(f2tf32(pa[2].x), f2tf32(pa[3].x), f2tf32(pa[2].y), f2tf32(pa[3].y));
        *(uint4*)(Ad + 12) = make_uint4(f2tf32(pa[2].z), f2tf32(pa[3].z), f2tf32(pa[2].w), f2tf32(pa[3].w));
        *(uint4*)(Bd + 0)  = make_uint4(f2tf32(pb[0].x), f2tf32(pb[1].x), f2tf32(pb[0].y), f2tf32(pb[1].y));
        *(uint4*)(Bd + 4)  = make_uint4(f2tf32(pb[0].z), f2tf32(pb[1].z), f2tf32(pb[0].w), f2tf32(pb[1].w));
        *(uint4*)(Bd + 8)  = make_uint4(f2tf32(pb[2].x), f2tf32(pb[3].x), f2tf32(pb[2].y), f2tf32(pb[3].y));
        *(uint4*)(Bd + 12) = make_uint4(f2tf32(pb[2].z), f2tf32(pb[3].z), f2tf32(pb[2].w), f2tf32(pb[3].w));
        __syncthreads();

        if (k0 + 32 < K) {
#pragma unroll
            for (int i = 0; i < 4; i++) {
                pa[i] = *(const float4*)(Ap + k0 + 32 + i * 4);
                pb[i] = *(const float4*)(Bp + k0 + 32 + i * 4);
            }
        }

#pragma unroll
        for (int ks = 0; ks < 4; ks++) {
            const int k8 = ks * 8;
            uint32_t afr[4][4], bfr[4][2];
#pragma unroll
            for (int mt = 0; mt < 4; mt++) {
                const int r0 = wm * 64 + mt * 16 + gr;
                uint2 a0 = *(const uint2*)&As[r0 * GP + k8 + 2 * cc];
                uint2 a1 = *(const uint2*)&As[(r0 + 8) * GP + k8 + 2 * cc];
                afr[mt][0] = a0.x; afr[mt][1] = a1.x;
                afr[mt][2] = a0.y; afr[mt][3] = a1.y;
            }
#pragma unroll
            for (int nt = 0; nt < 4; nt++) {
                const int nr = wn * 32 + nt * 8 + gr;
                uint2 b0 = *(const uint2*)&Bs[nr * GP + k8 + 2 * cc];
                bfr[nt][0] = b0.x; bfr[nt][1] = b0.y;
            }
#pragma unroll
            for (int mt = 0; mt < 4; mt++)
#pragma unroll
                for (int nt = 0; nt < 4; nt++)
                    mma_tf32(acc[mt][nt], afr[mt], bfr[nt]);
        }
        __syncthreads();
    }

    // epilogue
#pragma unroll
    for (int mt = 0; mt < 4; mt++) {
        const int r0 = bm + wm * 64 + mt * 16 + gr;
#pragma unroll
        for (int nt = 0; nt < 4; nt++) {
            const int cb = bn + wn * 32 + nt * 8 + 2 * cc;
            *(float2*)(C + (size_t)r0 * N + cb)       = make_float2(acc[mt][nt][0], acc[mt][nt][1]);
            *(float2*)(C + (size_t)(r0 + 8) * N + cb) = make_float2(acc[mt][nt][2], acc[mt][nt][3]);
        }
    }
}

// ---------------------------------------------------------------------------
// Flash attention, tf32 mma.sync (R6 structure + permuted-k K tiles,
// LDS.64 P fragments, V rows re-indexed to match the permutation).
//   Ks[64][68]: K rows with permuted k8 blocks -> b-frag = 1 LDS.64
//   Vs[64][68]: V rows linear; PV b-frags read rows (k8+2cc, k8+2cc+1)
//   Ps[128][68]: P written as uint2 at col 2cc == permuted layout; a-frag LDS.64
// ---------------------------------------------------------------------------
#define KSP 68
#define VSP 68
#define PSP 68
#define SM_KS (64 * KSP)
#define SM_VS (64 * VSP)
#define SM_PS (128 * PSP)
#define FLASH_SMEM ((SM_KS + SM_VS + SM_PS) * 4)

__global__ __launch_bounds__(256, 2)
void flash_tc(const float* __restrict__ Q, const float* __restrict__ K,
              const float* __restrict__ V, float* __restrict__ O,
              const int* __restrict__ maskflag)
{
    extern __shared__ float smf[];
    float* Ks = smf;                 // [n][d] pitch 68, permuted k
    float* Vs = Ks + SM_KS;          // [n][d] pitch 68, linear
    float* Ps = Vs + SM_VS;          // [m][n] pitch 68 (Q staging first, linear)

    const int tid  = threadIdx.x;
    const int lane = tid & 31;
    const int warp = tid >> 5;
    const int gr   = lane >> 2;
    const int cc   = lane & 3;
    const int bh   = blockIdx.y;
    const int bx   = blockIdx.x;
    const int m0   = bx * 128;
    const int wr0  = warp * 16;

    const float* Qb = Q + (size_t)bh * PS * PHD;
    const float* Kb = K + (size_t)bh * PS * PHD;
    const float* Vb = V + (size_t)bh * PS * PHD;
    float*       Ob = O + (size_t)bh * PS * PHD + (size_t)m0 * PHD;

    // stage Q (scaled, linear) then extract persistent tf32 fragments
    for (int t = tid; t < 2048; t += 256) {
        int r = t >> 4, c4 = (t & 15) << 2;
        float4 x = *(const float4*)(Qb + (size_t)(m0 + r) * PHD + c4);
        float* d = &Ps[r * PSP + c4];
        d[0] = x.x * 0.125f; d[1] = x.y * 0.125f;
        d[2] = x.z * 0.125f; d[3] = x.w * 0.125f;
    }
    __syncthreads();

    uint32_t qa[8][4];
#pragma unroll
    for (int s = 0; s < 8; s++) {
        const int k8 = s * 8;
        qa[s][0] = f2tf32(Ps[(wr0 + gr) * PSP + k8 + cc]);
        qa[s][1] = f2tf32(Ps[(wr0 + gr + 8) * PSP + k8 + cc]);
        qa[s][2] = f2tf32(Ps[(wr0 + gr) * PSP + k8 + cc + 4]);
        qa[s][3] = f2tf32(Ps[(wr0 + gr + 8) * PSP + k8 + cc + 4]);
    }
    __syncthreads();   // all warps done with Q staging area before P overwrites

    const bool causal = (*maskflag != 0);
    const int ntiles = causal ? (2 * bx + 2) : (PS / 64);

    float mr0 = -1e30f, mr1 = -1e30f, lr0 = 0.f, lr1 = 0.f;
    float o[8][4];
#pragma unroll
    for (int nt = 0; nt < 8; nt++)
#pragma unroll
        for (int r = 0; r < 4; r++) o[nt][r] = 0.f;

    for (int kt = 0; kt < ntiles; kt++) {
        const int n0 = kt * 64;

        // K: permuted k8 blocks, STS.128 pairs
        for (int t = tid; t < 512; t += 256) {
            int r = t >> 3, c8 = (t & 7) << 3;
            const float* src = Kb + (size_t)(n0 + r) * PHD + c8;
            float4 x0 = *(const float4*)(src);       // k c8..c8+3
            float4 x1 = *(const float4*)(src + 4);   // k c8+4..c8+7
            uint32_t* d = (uint32_t*)&Ks[r * KSP + c8];
            *(uint4*)(d)     = make_uint4(f2tf32(x0.x), f2tf32(x1.x), f2tf32(x0.y), f2tf32(x1.y));
            *(uint4*)(d + 4) = make_uint4(f2tf32(x0.z), f2tf32(x1.z), f2tf32(x0.w), f2tf32(x1.w));
        }
        // V: linear rows, vectorized store
        for (int t = tid; t < 1024; t += 256) {
            int r = t >> 4, c4 = (t & 15) << 2;
            float4 xv = *(const float4*)(Vb + (size_t)(n0 + r) * PHD + c4);
            *(uint4*)&Vs[r * VSP + c4] =
                make_uint4(f2tf32(xv.x), f2tf32(xv.y), f2tf32(xv.z), f2tf32(xv.w));
        }
        __syncthreads();

        // S = Q K^T
        float s[8][4];
#pragma unroll
        for (int nt = 0; nt < 8; nt++)
#pragma unroll
            for (int r = 0; r < 4; r++) s[nt][r] = 0.f;

#pragma unroll
        for (int ks = 0; ks < 8; ks++) {
            const int k8 = ks * 8;
#pragma unroll
            for (int nt = 0; nt < 8; nt++) {
                uint2 kb = *(const uint2*)&Ks[(nt * 8 + gr) * KSP + k8 + 2 * cc];
                uint32_t b[2] = {kb.x, kb.y};
                mma_tf32(s[nt], qa[ks], b);
            }
        }

        // causal mask
        const int rlo = m0 + wr0 + gr;
        const int rhi = rlo + 8;
        if (causal && (n0 + 63 > rlo)) {
#pragma unroll
            for (int nt = 0; nt < 8; nt++) {
                const int c0 = n0 + nt * 8 + 2 * cc;
                if (c0 > rlo)     s[nt][0] = -1e30f;
                if (c0 + 1 > rlo) s[nt][1] = -1e30f;
                if (c0 > rhi)     s[nt][2] = -1e30f;
                if (c0 + 1 > rhi) s[nt][3] = -1e30f;
            }
        }

        // online softmax (warp-local)
        float tl = -1e30f, th = -1e30f;
#pragma unroll
        for (int nt = 0; nt < 8; nt++) {
            tl = fmaxf(tl, fmaxf(s[nt][0], s[nt][1]));
            th = fmaxf(th, fmaxf(s[nt][2], s[nt][3]));
        }
        tl = fmaxf(tl, __shfl_xor_sync(0xffffffffu, tl, 1));
        tl = fmaxf(tl, __shfl_xor_sync(0xffffffffu, tl, 2));
        th = fmaxf(th, __shfl_xor_sync(0xffffffffu, th, 1));
        th = fmaxf(th, __shfl_xor_sync(0xffffffffu, th, 2));

        const float mn0 = fmaxf(mr0, tl);
        const float mn1 = fmaxf(mr1, th);
        const float al0 = __expf(mr0 - mn0);
        const float al1 = __expf(mr1 - mn1);

        float sl = 0.f, sh = 0.f;
#pragma unroll
        for (int nt = 0; nt < 8; nt++) {
            float p0 = __expf(s[nt][0] - mn0);
            float p1 = __expf(s[nt][1] - mn0);
            float p2 = __expf(s[nt][2] - mn1);
            float p3 = __expf(s[nt][3] - mn1);
            sl += p0 + p1; sh += p2 + p3;
            *(uint2*)&Ps[(wr0 + gr) * PSP + nt * 8 + 2 * cc]     = make_uint2(f2tf32(p0), f2tf32(p1));
            *(uint2*)&Ps[(wr0 + gr + 8) * PSP + nt * 8 + 2 * cc] = make_uint2(f2tf32(p2), f2tf32(p3));
        }
        sl += __shfl_xor_sync(0xffffffffu, sl, 1);
        sl += __shfl_xor_sync(0xffffffffu, sl, 2);
        sh += __shfl_xor_sync(0xffffffffu, sh, 1);
        sh += __shfl_xor_sync(0xffffffffu, sh, 2);

        lr0 = lr0 * al0 + sl;
        lr1 = lr1 * al1 + sh;
        mr0 = mn0; mr1 = mn1;

#pragma unroll
        for (int nt = 0; nt < 8; nt++) {
            o[nt][0] *= al0; o[nt][1] *= al0;
            o[nt][2] *= al1; o[nt][3] *= al1;
        }
        __syncwarp();   // warp-private P rows visible

        // O += P V. P cols stored (2cc,2cc+1) == permuted k slots; V rows
        // indexed (k8+2cc, k8+2cc+1) so both sides use the same permutation.
#pragma unroll
        for (int ks = 0; ks < 8; ks++) {
            const int k8 = ks * 8;
            uint2 pa0 = *(const uint2*)&Ps[(wr0 + gr) * PSP + k8 + 2 * cc];
            uint2 pa1 = *(const uint2*)&Ps[(wr0 + gr + 8) * PSP + k8 + 2 * cc];
            uint32_t a[4] = {pa0.x, pa1.x, pa0.y, pa1.y};
#pragma unroll
            for (int nt = 0; nt < 8; nt++) {
                uint32_t b[2];
                b[0] = __float_as_uint(Vs[(k8 + 2 * cc) * VSP + nt * 8 + gr]);
                b[1] = __float_as_uint(Vs[(k8 + 2 * cc + 1) * VSP + nt * 8 + gr]);
                mma_tf32(o[nt], a, b);
            }
        }
        __syncthreads();   // Ks/Vs consumed before next tile
    }

    // epilogue
    const float i0 = 1.0f / lr0;
    const float i1 = 1.0f / lr1;
#pragma unroll
    for (int nt = 0; nt < 8; nt++) {
        const int cb = nt * 8 + 2 * cc;
        *(float2*)(Ob + (size_t)(wr0 + gr) * PHD + cb) =
            make_float2(o[nt][0] * i0, o[nt][1] * i0);
        *(float2*)(Ob + (size_t)(wr0 + gr + 8) * PHD + cb) =
            make_float2(o[nt][2] * i1, o[nt][3] * i1);
    }
}

// ---------------------------------------------------------------------------
// Launch
// ---------------------------------------------------------------------------
extern "C" void kernel_launch(void* const* d_in, const int* in_sizes, int n_in,
                              void* d_out, int out_size)
{
    const float* q  = (const float*)d_in[0];
    const float* k  = (const float*)d_in[1];
    const float* v  = (const float*)d_in[2];
    const float* wq = (const float*)d_in[3];
    const float* wk = (const float*)d_in[4];
    const float* wv = (const float*)d_in[5];
    const float* wo = (const float*)d_in[6];
    const int*   am = (const int*)d_in[7];
    float* out = (float*)d_out;

    float *qp, *kp, *vp, *ao;
    cudaGetSymbolAddress((void**)&qp, g_qp);
    cudaGetSymbolAddress((void**)&kp, g_kp);
    cudaGetSymbolAddress((void**)&vp, g_vp);
    cudaGetSymbolAddress((void**)&ao, g_ao);

    cudaFuncSetAttribute(flash_tc, cudaFuncAttributeMaxDynamicSharedMemorySize, FLASH_SMEM);

    // fused Q/K/V projections (z = 0,1,2)
    dim3 gQKV(PE / 128, PM / 128, 3);   // (8, 32, 3)
    gemm_tf32<<<gQKV, 256>>>(q, wq, qp,  k, wk, kp,  v, wv, vp, PM, PE, PE);

    dim3 gAttn(PS / 128, PBH);          // (16, 32)
    flash_tc<<<gAttn, 256, FLASH_SMEM>>>(qp, kp, vp, ao, am);

    // output projection
    dim3 gO(PE / 128, PM / 128, 1);
    gemm_tf32<<<gO, 256>>>(ao, wo, out,  ao, wo, out,  ao, wo, out, PM, PE, PE);
}

// round 11
// speedup vs baseline: 1.2606x; 1.2393x over previous
#include <cuda_runtime.h>
#include <cuda_bf16.h>
#include <math_constants.h>
#include <cstdint>

// Problem constants
#define PB 2
#define PS 2048
#define PE 1024
#define PH 16
#define PHD 64
#define PBH (PB * PH)        // 32
#define PM (PB * PS)         // 4096

// ---------------------------------------------------------------------------
// helpers (sm_100-safe: mma.sync only)
// ---------------------------------------------------------------------------
__device__ __forceinline__ uint32_t f2tf32(float f) {
    uint32_t u; asm("cvt.rna.tf32.f32 %0, %1;" : "=r"(u) : "f"(f)); return u;
}
__device__ __forceinline__ void mma_tf32(float c[4], const uint32_t a[4], const uint32_t b[2]) {
    asm("mma.sync.aligned.m16n8k8.row.col.f32.tf32.tf32.f32 "
        "{%0,%1,%2,%3}, {%4,%5,%6,%7}, {%8,%9}, {%0,%1,%2,%3};"
        : "+f"(c[0]), "+f"(c[1]), "+f"(c[2]), "+f"(c[3])
        : "r"(a[0]), "r"(a[1]), "r"(a[2]), "r"(a[3]), "r"(b[0]), "r"(b[1]));
}

// ---------------------------------------------------------------------------
// Scratch (no cudaMalloc allowed)
// ---------------------------------------------------------------------------
__device__ float g_qp[PM * PE];
__device__ float g_kp[PM * PE];
__device__ float g_vp[PM * PE];
__device__ float g_ao[PM * PE];

// ---------------------------------------------------------------------------
// TF32 GEMM (R6 layouts + double-buffered smem, ONE sync per K-tile):
// C[M,N] = A[M,K] @ B[N,K]^T. CTA 128x128, 8 warps (2x4), warp tile 64x32,
// K-tile 32, pitch 36 (fragment bank = 4*gr + cc : conflict-free, measured R6).
// Schedule per tile t: LDG-prefetch(t+1) -> compute(buf) -> stage(buf^1) -> sync.
// Staging uses uint4 STS in LINEAR k-order (16B-aligned; 8-lane phases cover
// all 32 banks). tf32 cvt at staging time (fma pipe is idle there).
// ---------------------------------------------------------------------------
#define GP 36                         // smem pitch (words)
#define GT_BUF (128 * GP)             // words per matrix per buffer
#define GT_SMEM_BYTES (2 * 2 * GT_BUF * 4)   // 73728 B (2 buffers x (A+B))

__global__ __launch_bounds__(256, 2)
void gemm_tf32(const float* __restrict__ A0, const float* __restrict__ B0, float* __restrict__ C0,
               const float* __restrict__ A1, const float* __restrict__ B1, float* __restrict__ C1,
               const float* __restrict__ A2, const float* __restrict__ B2, float* __restrict__ C2,
               int M, int N, int K)
{
    extern __shared__ uint32_t S[];   // [buf][ A(128*36) | B(128*36) ]

    const float* A = A0; const float* B = B0; float* C = C0;
    if (blockIdx.z == 1) { A = A1; B = B1; C = C1; }
    else if (blockIdx.z == 2) { A = A2; B = B2; C = C2; }

    const int tid  = threadIdx.x;
    const int lane = tid & 31;
    const int warp = tid >> 5;
    const int wm   = warp >> 2;          // 0..1
    const int wn   = warp & 3;           // 0..3
    const int gr   = lane >> 2;          // 0..7
    const int cc   = lane & 3;           // 0..3

    const int bm = blockIdx.y * 128;
    const int bn = blockIdx.x * 128;

    const int lr = tid >> 1;             // 0..127
    const int lq = (tid & 1) * 16;       // 0 or 16

    const float* Ap = A + (size_t)(bm + lr) * K + lq;
    const float* Bp = B + (size_t)(bn + lr) * K + lq;

    float acc[4][4][4];
#pragma unroll
    for (int mt = 0; mt < 4; mt++)
#pragma unroll
        for (int nt = 0; nt < 4; nt++)
#pragma unroll
            for (int r = 0; r < 4; r++) acc[mt][nt][r] = 0.f;

    // register prefetch of tile 0
    float4 pa[4], pb[4];
#pragma unroll
    for (int i = 0; i < 4; i++) {
        pa[i] = *(const float4*)(Ap + i * 4);
        pb[i] = *(const float4*)(Bp + i * 4);
    }

    // stage helper: linear k-order, uint4 STS, cvt at store
    auto stage = [&](int buf) {
        uint32_t* Ad = S + buf * (2 * GT_BUF) + lr * GP + lq;
        uint32_t* Bd = Ad + GT_BUF;
#pragma unroll
        for (int i = 0; i < 4; i++) {
            *(uint4*)(Ad + i * 4) = make_uint4(f2tf32(pa[i].x), f2tf32(pa[i].y),
                                               f2tf32(pa[i].z), f2tf32(pa[i].w));
            *(uint4*)(Bd + i * 4) = make_uint4(f2tf32(pb[i].x), f2tf32(pb[i].y),
                                               f2tf32(pb[i].z), f2tf32(pb[i].w));
        }
    };

    stage(0);
    __syncthreads();

    const int NT = K / 32;   // 32
    int buf = 0;
    for (int t = 0; t < NT; t++) {
        const bool more = (t + 1 < NT);
        // prefetch next tile's GMEM into registers (latency hidden by compute)
        if (more) {
            const int ko = (t + 1) * 32;
#pragma unroll
            for (int i = 0; i < 4; i++) {
                pa[i] = *(const float4*)(Ap + ko + i * 4);
                pb[i] = *(const float4*)(Bp + ko + i * 4);
            }
        }

        // compute current buffer
        const uint32_t* As = S + buf * (2 * GT_BUF);
        const uint32_t* Bs = As + GT_BUF;
#pragma unroll
        for (int ks = 0; ks < 4; ks++) {
            const int k8 = ks * 8;
            uint32_t afr[4][4], bfr[4][2];
#pragma unroll
            for (int mt = 0; mt < 4; mt++) {
                const int r0 = wm * 64 + mt * 16 + gr;
                afr[mt][0] = As[r0 * GP + k8 + cc];
                afr[mt][1] = As[(r0 + 8) * GP + k8 + cc];
                afr[mt][2] = As[r0 * GP + k8 + cc + 4];
                afr[mt][3] = As[(r0 + 8) * GP + k8 + cc + 4];
            }
#pragma unroll
            for (int nt = 0; nt < 4; nt++) {
                const int nr = wn * 32 + nt * 8 + gr;
                bfr[nt][0] = Bs[nr * GP + k8 + cc];
                bfr[nt][1] = Bs[nr * GP + k8 + cc + 4];
            }
#pragma unroll
            for (int mt = 0; mt < 4; mt++)
#pragma unroll
                for (int nt = 0; nt < 4; nt++)
                    mma_tf32(acc[mt][nt], afr[mt], bfr[nt]);
        }

        // stage next tile into the other buffer, then one barrier
        if (more) {
            stage(buf ^ 1);
            __syncthreads();
            buf ^= 1;
        }
    }

    // epilogue
#pragma unroll
    for (int mt = 0; mt < 4; mt++) {
        const int r0 = bm + wm * 64 + mt * 16 + gr;
#pragma unroll
        for (int nt = 0; nt < 4; nt++) {
            const int cb = bn + wn * 32 + nt * 8 + 2 * cc;
            *(float2*)(C + (size_t)r0 * N + cb)       = make_float2(acc[mt][nt][0], acc[mt][nt][1]);
            *(float2*)(C + (size_t)(r0 + 8) * N + cb) = make_float2(acc[mt][nt][2], acc[mt][nt][3]);
        }
    }
}

// ---------------------------------------------------------------------------
// Flash attention, tf32 mma.sync (EXACT R6 version: 601us total baseline)
// ---------------------------------------------------------------------------
#define KSP 68
#define VSP 72
#define PSP 68
#define SM_KS (64 * KSP)
#define SM_VS (64 * VSP)
#define SM_PS (128 * PSP)
#define FLASH_SMEM ((SM_KS + SM_VS + SM_PS) * 4)

__global__ __launch_bounds__(256, 2)
void flash_tc(const float* __restrict__ Q, const float* __restrict__ K,
              const float* __restrict__ V, float* __restrict__ O,
              const int* __restrict__ maskflag)
{
    extern __shared__ float smf[];
    float* Ks = smf;                 // [n][d] pitch 68
    float* Vs = Ks + SM_KS;          // [n][d] pitch 72
    float* Ps = Vs + SM_VS;          // [m][n] pitch 68 (Q staging first)

    const int tid  = threadIdx.x;
    const int lane = tid & 31;
    const int warp = tid >> 5;
    const int gr   = lane >> 2;
    const int cc   = lane & 3;
    const int bh   = blockIdx.y;
    const int bx   = blockIdx.x;
    const int m0   = bx * 128;
    const int wr0  = warp * 16;

    const float* Qb = Q + (size_t)bh * PS * PHD;
    const float* Kb = K + (size_t)bh * PS * PHD;
    const float* Vb = V + (size_t)bh * PS * PHD;
    float*       Ob = O + (size_t)bh * PS * PHD + (size_t)m0 * PHD;

    for (int t = tid; t < 2048; t += 256) {
        int r = t >> 4, c4 = (t & 15) << 2;
        float4 x = *(const float4*)(Qb + (size_t)(m0 + r) * PHD + c4);
        float* d = &Ps[r * PSP + c4];
        d[0] = x.x * 0.125f; d[1] = x.y * 0.125f;
        d[2] = x.z * 0.125f; d[3] = x.w * 0.125f;
    }
    __syncthreads();

    uint32_t qa[8][4];
#pragma unroll
    for (int s = 0; s < 8; s++) {
        const int k8 = s * 8;
        qa[s][0] = f2tf32(Ps[(wr0 + gr) * PSP + k8 + cc]);
        qa[s][1] = f2tf32(Ps[(wr0 + gr + 8) * PSP + k8 + cc]);
        qa[s][2] = f2tf32(Ps[(wr0 + gr) * PSP + k8 + cc + 4]);
        qa[s][3] = f2tf32(Ps[(wr0 + gr + 8) * PSP + k8 + cc + 4]);
    }
    __syncwarp();

    const bool causal = (*maskflag != 0);
    const int ntiles = causal ? (2 * bx + 2) : (PS / 64);

    float mr0 = -1e30f, mr1 = -1e30f, lr0 = 0.f, lr1 = 0.f;
    float o[8][4];
#pragma unroll
    for (int nt = 0; nt < 8; nt++)
#pragma unroll
        for (int r = 0; r < 4; r++) o[nt][r] = 0.f;

    for (int kt = 0; kt < ntiles; kt++) {
        const int n0 = kt * 64;

        for (int t = tid; t < 1024; t += 256) {
            int r = t >> 4, c4 = (t & 15) << 2;
            float4 xk = *(const float4*)(Kb + (size_t)(n0 + r) * PHD + c4);
            float* kd = &Ks[r * KSP + c4];
            kd[0] = __uint_as_float(f2tf32(xk.x)); kd[1] = __uint_as_float(f2tf32(xk.y));
            kd[2] = __uint_as_float(f2tf32(xk.z)); kd[3] = __uint_as_float(f2tf32(xk.w));
            float4 xv = *(const float4*)(Vb + (size_t)(n0 + r) * PHD + c4);
            float* vd = &Vs[r * VSP + c4];
            vd[0] = __uint_as_float(f2tf32(xv.x)); vd[1] = __uint_as_float(f2tf32(xv.y));
            vd[2] = __uint_as_float(f2tf32(xv.z)); vd[3] = __uint_as_float(f2tf32(xv.w));
        }
        __syncthreads();

        float s[8][4];
#pragma unroll
        for (int nt = 0; nt < 8; nt++)
#pragma unroll
            for (int r = 0; r < 4; r++) s[nt][r] = 0.f;

#pragma unroll
        for (int ks = 0; ks < 8; ks++) {
            const int k8 = ks * 8;
#pragma unroll
            for (int nt = 0; nt < 8; nt++) {
                uint32_t b[2];
                b[0] = __float_as_uint(Ks[(nt * 8 + gr) * KSP + k8 + cc]);
                b[1] = __float_as_uint(Ks[(nt * 8 + gr) * KSP + k8 + cc + 4]);
                mma_tf32(s[nt], qa[ks], b);
            }
        }

        const int rlo = m0 + wr0 + gr;
        const int rhi = rlo + 8;
        if (causal && (n0 + 63 > rlo)) {
#pragma unroll
            for (int nt = 0; nt < 8; nt++) {
                const int c0 = n0 + nt * 8 + 2 * cc;
                if (c0 > rlo)     s[nt][0] = -1e30f;
                if (c0 + 1 > rlo) s[nt][1] = -1e30f;
                if (c0 > rhi)     s[nt][2] = -1e30f;
                if (c0 + 1 > rhi) s[nt][3] = -1e30f;
            }
        }

        float tl = -1e30f, th = -1e30f;
#pragma unroll
        for (int nt = 0; nt < 8; nt++) {
            tl = fmaxf(tl, fmaxf(s[nt][0], s[nt][1]));
            th = fmaxf(th, fmaxf(s[nt][2], s[nt][3]));
        }
        tl = fmaxf(tl, __shfl_xor_sync(0xffffffffu, tl, 1));
        tl = fmaxf(tl, __shfl_xor_sync(0xffffffffu, tl, 2));
        th = fmaxf(th, __shfl_xor_sync(0xffffffffu, th, 1));
        th = fmaxf(th, __shfl_xor_sync(0xffffffffu, th, 2));

        const float mn0 = fmaxf(mr0, tl);
        const float mn1 = fmaxf(mr1, th);
        const float al0 = __expf(mr0 - mn0);
        const float al1 = __expf(mr1 - mn1);

        float sl = 0.f, sh = 0.f;
#pragma unroll
        for (int nt = 0; nt < 8; nt++) {
            float p0 = __expf(s[nt][0] - mn0);
            float p1 = __expf(s[nt][1] - mn0);
            float p2 = __expf(s[nt][2] - mn1);
            float p3 = __expf(s[nt][3] - mn1);
            sl += p0 + p1; sh += p2 + p3;
            uint2 w0 = make_uint2(f2tf32(p0), f2tf32(p1));
            uint2 w1 = make_uint2(f2tf32(p2), f2tf32(p3));
            *(uint2*)&Ps[(wr0 + gr) * PSP + nt * 8 + 2 * cc]     = w0;
            *(uint2*)&Ps[(wr0 + gr + 8) * PSP + nt * 8 + 2 * cc] = w1;
        }
        sl += __shfl_xor_sync(0xffffffffu, sl, 1);
        sl += __shfl_xor_sync(0xffffffffu, sl, 2);
        sh += __shfl_xor_sync(0xffffffffu, sh, 1);
        sh += __shfl_xor_sync(0xffffffffu, sh, 2);

        lr0 = lr0 * al0 + sl;
        lr1 = lr1 * al1 + sh;
        mr0 = mn0; mr1 = mn1;

#pragma unroll
        for (int nt = 0; nt < 8; nt++) {
            o[nt][0] *= al0; o[nt][1] *= al0;
            o[nt][2] *= al1; o[nt][3] *= al1;
        }
        __syncwarp();

#pragma unroll
        for (int ks = 0; ks < 8; ks++) {
            const int k8 = ks * 8;
            uint32_t a[4];
            a[0] = __float_as_uint(Ps[(wr0 + gr) * PSP + k8 + cc]);
            a[1] = __float_as_uint(Ps[(wr0 + gr + 8) * PSP + k8 + cc]);
            a[2] = __float_as_uint(Ps[(wr0 + gr) * PSP + k8 + cc + 4]);
            a[3] = __float_as_uint(Ps[(wr0 + gr + 8) * PSP + k8 + cc + 4]);
#pragma unroll
            for (int nt = 0; nt < 8; nt++) {
                uint32_t b[2];
                b[0] = __float_as_uint(Vs[(k8 + cc) * VSP + nt * 8 + gr]);
                b[1] = __float_as_uint(Vs[(k8 + cc + 4) * VSP + nt * 8 + gr]);
                mma_tf32(o[nt], a, b);
            }
        }
        __syncthreads();
    }

    const float i0 = 1.0f / lr0;
    const float i1 = 1.0f / lr1;
#pragma unroll
    for (int nt = 0; nt < 8; nt++) {
        const int cb = nt * 8 + 2 * cc;
        *(float2*)(Ob + (size_t)(wr0 + gr) * PHD + cb) =
            make_float2(o[nt][0] * i0, o[nt][1] * i0);
        *(float2*)(Ob + (size_t)(wr0 + gr + 8) * PHD + cb) =
            make_float2(o[nt][2] * i1, o[nt][3] * i1);
    }
}

// ---------------------------------------------------------------------------
// Launch
// ---------------------------------------------------------------------------
extern "C" void kernel_launch(void* const* d_in, const int* in_sizes, int n_in,
                              void* d_out, int out_size)
{
    const float* q  = (const float*)d_in[0];
    const float* k  = (const float*)d_in[1];
    const float* v  = (const float*)d_in[2];
    const float* wq = (const float*)d_in[3];
    const float* wk = (const float*)d_in[4];
    const float* wv = (const float*)d_in[5];
    const float* wo = (const float*)d_in[6];
    const int*   am = (const int*)d_in[7];
    float* out = (float*)d_out;

    float *qp, *kp, *vp, *ao;
    cudaGetSymbolAddress((void**)&qp, g_qp);
    cudaGetSymbolAddress((void**)&kp, g_kp);
    cudaGetSymbolAddress((void**)&vp, g_vp);
    cudaGetSymbolAddress((void**)&ao, g_ao);

    cudaFuncSetAttribute(gemm_tf32, cudaFuncAttributeMaxDynamicSharedMemorySize, GT_SMEM_BYTES);
    cudaFuncSetAttribute(flash_tc, cudaFuncAttributeMaxDynamicSharedMemorySize, FLASH_SMEM);

    // fused Q/K/V projections (z = 0,1,2)
    dim3 gQKV(PE / 128, PM / 128, 3);   // (8, 32, 3)
    gemm_tf32<<<gQKV, 256, GT_SMEM_BYTES>>>(q, wq, qp,  k, wk, kp,  v, wv, vp, PM, PE, PE);

    dim3 gAttn(PS / 128, PBH);          // (16, 32)
    flash_tc<<<gAttn, 256, FLASH_SMEM>>>(qp, kp, vp, ao, am);

    // output projection
    dim3 gO(PE / 128, PM / 128, 1);
    gemm_tf32<<<gO, 256, GT_SMEM_BYTES>>>(ao, wo, out,  ao, wo, out,  ao, wo, out, PM, PE, PE);
}

// round 14
// speedup vs baseline: 1.4444x; 1.1459x over previous
#include <cuda_runtime.h>
#include <cuda_fp16.h>
#include <math_constants.h>
#include <cstdint>
#include <cstring>

// Problem constants
#define PB 2
#define PS 2048
#define PE 1024
#define PH 16
#define PHD 64
#define PBH (PB * PH)        // 32
#define PM (PB * PS)         // 4096

// ---------------------------------------------------------------------------
// helpers (sm_100-safe: mma.sync only)
// ---------------------------------------------------------------------------
__device__ __forceinline__ uint32_t f2tf32(float f) {
    uint32_t u; asm("cvt.rna.tf32.f32 %0, %1;" : "=r"(u) : "f"(f)); return u;
}
__device__ __forceinline__ void mma_tf32(float c[4], const uint32_t a[4], const uint32_t b[2]) {
    asm("mma.sync.aligned.m16n8k8.row.col.f32.tf32.tf32.f32 "
        "{%0,%1,%2,%3}, {%4,%5,%6,%7}, {%8,%9}, {%0,%1,%2,%3};"
        : "+f"(c[0]), "+f"(c[1]), "+f"(c[2]), "+f"(c[3])
        : "r"(a[0]), "r"(a[1]), "r"(a[2]), "r"(a[3]), "r"(b[0]), "r"(b[1]));
}
__device__ __forceinline__ uint32_t h2pack(float x, float y) {
    __half2 h = __floats2half2_rn(x, y);
    uint32_t u;
    memcpy(&u, &h, 4);
    return u;
}
__device__ __forceinline__ void mma_f16(float c[4], const uint32_t a[4], const uint32_t b[2]) {
    asm("mma.sync.aligned.m16n8k16.row.col.f32.f16.f16.f32 "
        "{%0,%1,%2,%3}, {%4,%5,%6,%7}, {%8,%9}, {%0,%1,%2,%3};"
        : "+f"(c[0]), "+f"(c[1]), "+f"(c[2]), "+f"(c[3])
        : "r"(a[0]), "r"(a[1]), "r"(a[2]), "r"(a[3]), "r"(b[0]), "r"(b[1]));
}

// ---------------------------------------------------------------------------
// Scratch (no cudaMalloc allowed)
// ---------------------------------------------------------------------------
__device__ float g_qp[PM * PE];
__device__ float g_kp[PM * PE];
__device__ float g_vp[PM * PE];
__device__ float g_ao[PM * PE];

// ---------------------------------------------------------------------------
// TF32 GEMM (EXACT R11 version — proven 278.6us QKV / 93us O-proj):
// C[M,N] = A[M,K] @ B[N,K]^T. CTA 128x128, 8 warps (2x4), warp tile 64x32,
// K-tile 32, pitch 36, double-buffered, one sync per K-tile.
// ---------------------------------------------------------------------------
#define GP 36                         // smem pitch (words)
#define GT_BUF (128 * GP)             // words per matrix per buffer
#define GT_SMEM_BYTES (2 * 2 * GT_BUF * 4)   // 73728 B

__global__ __launch_bounds__(256, 2)
void gemm_tf32(const float* __restrict__ A0, const float* __restrict__ B0, float* __restrict__ C0,
               const float* __restrict__ A1, const float* __restrict__ B1, float* __restrict__ C1,
               const float* __restrict__ A2, const float* __restrict__ B2, float* __restrict__ C2,
               int M, int N, int K)
{
    extern __shared__ uint32_t S[];

    const float* A = A0; const float* B = B0; float* C = C0;
    if (blockIdx.z == 1) { A = A1; B = B1; C = C1; }
    else if (blockIdx.z == 2) { A = A2; B = B2; C = C2; }

    const int tid  = threadIdx.x;
    const int lane = tid & 31;
    const int warp = tid >> 5;
    const int wm   = warp >> 2;
    const int wn   = warp & 3;
    const int gr   = lane >> 2;
    const int cc   = lane & 3;

    const int bm = blockIdx.y * 128;
    const int bn = blockIdx.x * 128;

    const int lr = tid >> 1;
    const int lq = (tid & 1) * 16;

    const float* Ap = A + (size_t)(bm + lr) * K + lq;
    const float* Bp = B + (size_t)(bn + lr) * K + lq;

    float acc[4][4][4];
#pragma unroll
    for (int mt = 0; mt < 4; mt++)
#pragma unroll
        for (int nt = 0; nt < 4; nt++)
#pragma unroll
            for (int r = 0; r < 4; r++) acc[mt][nt][r] = 0.f;

    float4 pa[4], pb[4];
#pragma unroll
    for (int i = 0; i < 4; i++) {
        pa[i] = *(const float4*)(Ap + i * 4);
        pb[i] = *(const float4*)(Bp + i * 4);
    }

    auto stage = [&](int buf) {
        uint32_t* Ad = S + buf * (2 * GT_BUF) + lr * GP + lq;
        uint32_t* Bd = Ad + GT_BUF;
#pragma unroll
        for (int i = 0; i < 4; i++) {
            *(uint4*)(Ad + i * 4) = make_uint4(f2tf32(pa[i].x), f2tf32(pa[i].y),
                                               f2tf32(pa[i].z), f2tf32(pa[i].w));
            *(uint4*)(Bd + i * 4) = make_uint4(f2tf32(pb[i].x), f2tf32(pb[i].y),
                                               f2tf32(pb[i].z), f2tf32(pb[i].w));
        }
    };

    stage(0);
    __syncthreads();

    const int NT = K / 32;
    int buf = 0;
    for (int t = 0; t < NT; t++) {
        const bool more = (t + 1 < NT);
        if (more) {
            const int ko = (t + 1) * 32;
#pragma unroll
            for (int i = 0; i < 4; i++) {
                pa[i] = *(const float4*)(Ap + ko + i * 4);
                pb[i] = *(const float4*)(Bp + ko + i * 4);
            }
        }

        const uint32_t* As = S + buf * (2 * GT_BUF);
        const uint32_t* Bs = As + GT_BUF;
#pragma unroll
        for (int ks = 0; ks < 4; ks++) {
            const int k8 = ks * 8;
            uint32_t afr[4][4], bfr[4][2];
#pragma unroll
            for (int mt = 0; mt < 4; mt++) {
                const int r0 = wm * 64 + mt * 16 + gr;
                afr[mt][0] = As[r0 * GP + k8 + cc];
                afr[mt][1] = As[(r0 + 8) * GP + k8 + cc];
                afr[mt][2] = As[r0 * GP + k8 + cc + 4];
                afr[mt][3] = As[(r0 + 8) * GP + k8 + cc + 4];
            }
#pragma unroll
            for (int nt = 0; nt < 4; nt++) {
                const int nr = wn * 32 + nt * 8 + gr;
                bfr[nt][0] = Bs[nr * GP + k8 + cc];
                bfr[nt][1] = Bs[nr * GP + k8 + cc + 4];
            }
#pragma unroll
            for (int mt = 0; mt < 4; mt++)
#pragma unroll
                for (int nt = 0; nt < 4; nt++)
                    mma_tf32(acc[mt][nt], afr[mt], bfr[nt]);
        }

        if (more) {
            stage(buf ^ 1);
            __syncthreads();
            buf ^= 1;
        }
    }

#pragma unroll
    for (int mt = 0; mt < 4; mt++) {
        const int r0 = bm + wm * 64 + mt * 16 + gr;
#pragma unroll
        for (int nt = 0; nt < 4; nt++) {
            const int cb = bn + wn * 32 + nt * 8 + 2 * cc;
            *(float2*)(C + (size_t)r0 * N + cb)       = make_float2(acc[mt][nt][0], acc[mt][nt][1]);
            *(float2*)(C + (size_t)(r0 + 8) * N + cb) = make_float2(acc[mt][nt][2], acc[mt][nt][3]);
        }
    }
}

// ---------------------------------------------------------------------------
// Flash attention, fp16 mma.sync (fp32 softmax/accum).
// FIX vs R12/R13: Vp pitch was 40 half2 but d-dim is 64 -> rows overlapped
// (the 0.859 rel_err). Now VP2=72: row holds 64 d + 8 pad; PV b-frag word
// bank = (8cc + gr + 8nt) mod 32 — bijective over the warp, conflict-free.
//   Ks[64][72 halves]: K rows (d along row)
//   Vp[32][72 half2]:  V seq-pairs: Vp[p][d] = (V[2p][d], V[2p+1][d])
//   Ps[128][72 halves]: Q staging, then P rows (warp-private)
// ---------------------------------------------------------------------------
#define KS16 72
#define PS16 72
#define VP2  72

__global__ __launch_bounds__(256, 2)
void flash_f16(const float* __restrict__ Q, const float* __restrict__ K,
               const float* __restrict__ V, float* __restrict__ O,
               const int* __restrict__ maskflag)
{
    __shared__ __half  Ks[64 * KS16];        // 9216 B
    __shared__ __half2 Vp[32 * VP2];         // 9216 B
    __shared__ __half  Ps[128 * PS16];       // 18432 B

    const int tid  = threadIdx.x;
    const int lane = tid & 31;
    const int warp = tid >> 5;
    const int gr   = lane >> 2;
    const int cc   = lane & 3;
    const int bh   = blockIdx.y;
    const int bx   = blockIdx.x;
    const int m0   = bx * 128;
    const int wr0  = warp * 16;

    const float* Qb = Q + (size_t)bh * PS * PHD;
    const float* Kb = K + (size_t)bh * PS * PHD;
    const float* Vb = V + (size_t)bh * PS * PHD;
    float*       Ob = O + (size_t)bh * PS * PHD + (size_t)m0 * PHD;

    // stage Q (scaled 1/8) as fp16 into Ps
    for (int t = tid; t < 1024; t += 256) {
        int r = t >> 3, c8 = (t & 7) << 3;
        const float* src = Qb + (size_t)(m0 + r) * PHD + c8;
        float4 x0 = *(const float4*)(src);
        float4 x1 = *(const float4*)(src + 4);
        *(uint4*)&Ps[r * PS16 + c8] = make_uint4(
            h2pack(x0.x * 0.125f, x0.y * 0.125f), h2pack(x0.z * 0.125f, x0.w * 0.125f),
            h2pack(x1.x * 0.125f, x1.y * 0.125f), h2pack(x1.z * 0.125f, x1.w * 0.125f));
    }
    __syncthreads();

    // persistent Q fragments (m16n8k16 A: a0=(gr,2cc) a1=(gr+8,2cc) a2=(gr,2cc+8) a3=(gr+8,2cc+8))
    uint32_t qa[4][4];
#pragma unroll
    for (int s = 0; s < 4; s++) {
        const int kh = s * 16 + 2 * cc;
        qa[s][0] = *(const uint32_t*)&Ps[(wr0 + gr) * PS16 + kh];
        qa[s][1] = *(const uint32_t*)&Ps[(wr0 + gr + 8) * PS16 + kh];
        qa[s][2] = *(const uint32_t*)&Ps[(wr0 + gr) * PS16 + kh + 8];
        qa[s][3] = *(const uint32_t*)&Ps[(wr0 + gr + 8) * PS16 + kh + 8];
    }
    __syncwarp();

    const bool causal = (*maskflag != 0);
    const int ntiles = causal ? (2 * bx + 2) : (PS / 64);

    float mr0 = -1e30f, mr1 = -1e30f, lr0 = 0.f, lr1 = 0.f;
    float o[8][4];
#pragma unroll
    for (int nt = 0; nt < 8; nt++)
#pragma unroll
        for (int r = 0; r < 4; r++) o[nt][r] = 0.f;

    for (int kt = 0; kt < ntiles; kt++) {
        const int n0 = kt * 64;

        for (int t = tid; t < 512; t += 256) {
            int r = t >> 3, c8 = (t & 7) << 3;
            const float* src = Kb + (size_t)(n0 + r) * PHD + c8;
            float4 x0 = *(const float4*)(src);
            float4 x1 = *(const float4*)(src + 4);
            *(uint4*)&Ks[r * KS16 + c8] = make_uint4(
                h2pack(x0.x, x0.y), h2pack(x0.z, x0.w),
                h2pack(x1.x, x1.y), h2pack(x1.z, x1.w));
        }
        for (int t = tid; t < 512; t += 256) {
            int p = t >> 4, c4 = (t & 15) << 2;
            const float* s0 = Vb + (size_t)(n0 + 2 * p) * PHD + c4;
            const float* s1 = s0 + PHD;
            float4 x0 = *(const float4*)s0;
            float4 x1 = *(const float4*)s1;
            *(uint4*)&Vp[p * VP2 + c4] = make_uint4(
                h2pack(x0.x, x1.x), h2pack(x0.y, x1.y),
                h2pack(x0.z, x1.z), h2pack(x0.w, x1.w));
        }
        __syncthreads();

        // S = Q K^T
        float s[8][4];
#pragma unroll
        for (int nt = 0; nt < 8; nt++)
#pragma unroll
            for (int r = 0; r < 4; r++) s[nt][r] = 0.f;

#pragma unroll
        for (int ks = 0; ks < 4; ks++) {
            const int kh = ks * 16 + 2 * cc;
#pragma unroll
            for (int nt = 0; nt < 8; nt++) {
                uint32_t b[2];
                b[0] = *(const uint32_t*)&Ks[(nt * 8 + gr) * KS16 + kh];
                b[1] = *(const uint32_t*)&Ks[(nt * 8 + gr) * KS16 + kh + 8];
                mma_f16(s[nt], qa[ks], b);
            }
        }

        // causal mask
        const int rlo = m0 + wr0 + gr;
        const int rhi = rlo + 8;
        if (causal && (n0 + 63 > rlo)) {
#pragma unroll
            for (int nt = 0; nt < 8; nt++) {
                const int c0 = n0 + nt * 8 + 2 * cc;
                if (c0 > rlo)     s[nt][0] = -1e30f;
                if (c0 + 1 > rlo) s[nt][1] = -1e30f;
                if (c0 > rhi)     s[nt][2] = -1e30f;
                if (c0 + 1 > rhi) s[nt][3] = -1e30f;
            }
        }

        // online softmax (warp-local; quad reduce over cc)
        float tl = -1e30f, th = -1e30f;
#pragma unroll
        for (int nt = 0; nt < 8; nt++) {
            tl = fmaxf(tl, fmaxf(s[nt][0], s[nt][1]));
            th = fmaxf(th, fmaxf(s[nt][2], s[nt][3]));
        }
        tl = fmaxf(tl, __shfl_xor_sync(0xffffffffu, tl, 1));
        tl = fmaxf(tl, __shfl_xor_sync(0xffffffffu, tl, 2));
        th = fmaxf(th, __shfl_xor_sync(0xffffffffu, th, 1));
        th = fmaxf(th, __shfl_xor_sync(0xffffffffu, th, 2));

        const float mn0 = fmaxf(mr0, tl);
        const float mn1 = fmaxf(mr1, th);
        const float al0 = __expf(mr0 - mn0);
        const float al1 = __expf(mr1 - mn1);

        float sl = 0.f, sh = 0.f;
#pragma unroll
        for (int nt = 0; nt < 8; nt++) {
            float p0 = __expf(s[nt][0] - mn0);
            float p1 = __expf(s[nt][1] - mn0);
            float p2 = __expf(s[nt][2] - mn1);
            float p3 = __expf(s[nt][3] - mn1);
            sl += p0 + p1; sh += p2 + p3;
            *(uint32_t*)&Ps[(wr0 + gr) * PS16 + nt * 8 + 2 * cc]     = h2pack(p0, p1);
            *(uint32_t*)&Ps[(wr0 + gr + 8) * PS16 + nt * 8 + 2 * cc] = h2pack(p2, p3);
        }
        sl += __shfl_xor_sync(0xffffffffu, sl, 1);
        sl += __shfl_xor_sync(0xffffffffu, sl, 2);
        sh += __shfl_xor_sync(0xffffffffu, sh, 1);
        sh += __shfl_xor_sync(0xffffffffu, sh, 2);

        lr0 = lr0 * al0 + sl;
        lr1 = lr1 * al1 + sh;
        mr0 = mn0; mr1 = mn1;

#pragma unroll
        for (int nt = 0; nt < 8; nt++) {
            o[nt][0] *= al0; o[nt][1] *= al0;
            o[nt][2] *= al1; o[nt][3] *= al1;
        }
        __syncwarp();

        // O += P V  (4 k16 steps over 64 kv rows; V pair row pp = ks*8+cc)
#pragma unroll
        for (int ks = 0; ks < 4; ks++) {
            const int kh = ks * 16 + 2 * cc;
            const int pp = ks * 8 + cc;
            uint32_t a[4];
            a[0] = *(const uint32_t*)&Ps[(wr0 + gr) * PS16 + kh];
            a[1] = *(const uint32_t*)&Ps[(wr0 + gr + 8) * PS16 + kh];
            a[2] = *(const uint32_t*)&Ps[(wr0 + gr) * PS16 + kh + 8];
            a[3] = *(const uint32_t*)&Ps[(wr0 + gr + 8) * PS16 + kh + 8];
#pragma unroll
            for (int nt = 0; nt < 8; nt++) {
                uint32_t b[2];
                memcpy(&b[0], &Vp[pp * VP2 + nt * 8 + gr], 4);
                memcpy(&b[1], &Vp[(pp + 4) * VP2 + nt * 8 + gr], 4);
                mma_f16(o[nt], a, b);
            }
        }
        __syncthreads();
    }

    // epilogue
    const float i0 = 1.0f / lr0;
    const float i1 = 1.0f / lr1;
#pragma unroll
    for (int nt = 0; nt < 8; nt++) {
        const int cb = nt * 8 + 2 * cc;
        *(float2*)(Ob + (size_t)(wr0 + gr) * PHD + cb) =
            make_float2(o[nt][0] * i0, o[nt][1] * i0);
        *(float2*)(Ob + (size_t)(wr0 + gr + 8) * PHD + cb) =
            make_float2(o[nt][2] * i1, o[nt][3] * i1);
    }
}

// ---------------------------------------------------------------------------
// Launch
// ---------------------------------------------------------------------------
extern "C" void kernel_launch(void* const* d_in, const int* in_sizes, int n_in,
                              void* d_out, int out_size)
{
    const float* q  = (const float*)d_in[0];
    const float* k  = (const float*)d_in[1];
    const float* v  = (const float*)d_in[2];
    const float* wq = (const float*)d_in[3];
    const float* wk = (const float*)d_in[4];
    const float* wv = (const float*)d_in[5];
    const float* wo = (const float*)d_in[6];
    const int*   am = (const int*)d_in[7];
    float* out = (float*)d_out;

    float *qp, *kp, *vp, *ao;
    cudaGetSymbolAddress((void**)&qp, g_qp);
    cudaGetSymbolAddress((void**)&kp, g_kp);
    cudaGetSymbolAddress((void**)&vp, g_vp);
    cudaGetSymbolAddress((void**)&ao, g_ao);

    cudaFuncSetAttribute(gemm_tf32, cudaFuncAttributeMaxDynamicSharedMemorySize, GT_SMEM_BYTES);

    // fused Q/K/V projections (z = 0,1,2)
    dim3 gQKV(PE / 128, PM / 128, 3);   // (8, 32, 3)
    gemm_tf32<<<gQKV, 256, GT_SMEM_BYTES>>>(q, wq, qp,  k, wk, kp,  v, wv, vp, PM, PE, PE);

    dim3 gAttn(PS / 128, PBH);          // (16, 32)
    flash_f16<<<gAttn, 256>>>(qp, kp, vp, ao, am);

    // output projection
    dim3 gO(PE / 128, PM / 128, 1);
    gemm_tf32<<<gO, 256, GT_SMEM_BYTES>>>(ao, wo, out,  ao, wo, out,  ao, wo, out, PM, PE, PE);
}